// round 5
// baseline (speedup 1.0000x reference)
#include <cuda_runtime.h>

// AdditiveAttention: B=4, Q=512, K=512, H=256, E=256, DV=256
//   q = queries @ W_q^T            [B,Q,H]
//   k = keys    @ W_k^T            [B,K,H]
//   s[b,q,k] = sum_h w_v[h] * tanh(q[b,q,h] + k[b,k,h])
//   attn = softmax_k(s);  out = attn @ values   [B,Q,Dv]
//
// Key trick: tanh(q+k) = (tq + tk) / (1 + tq*tk) with tq=tanh(q), tk=tanh(k)
// precomputed in the projection epilogue (1M tanh instead of 268M).
// Inner loop uses MUFU.RCP (rt=8, 2x the element rate of MUFU.TANH).

#define BB 4
#define QQ 512
#define KK 512
#define HH 256
#define EE 256
#define DVV 256

// scratch (device globals: no allocations allowed)
__device__ float4 g_qv[BB * QQ * HH / 4];   // tq = tanh(q_proj), 2 MB
__device__ float4 g_kv[BB * KK * HH / 4];   // tk = tanh(k_proj), 2 MB
__device__ float4 g_sv[BB * QQ * KK / 4];   // scores, 4 MB

__device__ __forceinline__ float tanh_fast(float x) {
    float y;
    asm("tanh.approx.f32 %0, %1;" : "=f"(y) : "f"(x));
    return y;
}
__device__ __forceinline__ float rcp_fast(float x) {
    float y;
    asm("rcp.approx.f32 %0, %1;" : "=f"(y) : "f"(x));
    return y;
}

// ---------------------------------------------------------------------------
// Projection GEMM + tanh epilogue: C[r][h] = tanh( sum_e A[r][e] * W[h][e] )
// 64x64 tile, 256 threads, 4x4 register tile, e-chunk 32. (R3-best shape.)
// ---------------------------------------------------------------------------
__global__ __launch_bounds__(256) void proj_kernel(
    const float* __restrict__ Aq, const float* __restrict__ Wq,
    const float* __restrict__ Ak, const float* __restrict__ Wk)
{
    const float* A; const float* W; float* C;
    if (blockIdx.z == 0) { A = Aq; W = Wq; C = (float*)g_qv; }
    else                 { A = Ak; W = Wk; C = (float*)g_kv; }

    const int row0 = blockIdx.x * 64;
    const int col0 = blockIdx.y * 64;

    __shared__ __align__(16) float As[32][68];
    __shared__ __align__(16) float Ws[32][68];

    const int tid = threadIdx.x;
    const int tx = tid & 15;
    const int ty = tid >> 4;

    float c[4][4];
#pragma unroll
    for (int i = 0; i < 4; ++i)
#pragma unroll
        for (int j = 0; j < 4; ++j) c[i][j] = 0.0f;

    for (int e0 = 0; e0 < EE; e0 += 32) {
        __syncthreads();
#pragma unroll
        for (int i = 0; i < 2; ++i) {
            const int idx = tid + i * 256;
            const int r  = idx >> 3;
            const int e8 = idx & 7;
            float4 va = *(const float4*)(A + (size_t)(row0 + r) * EE + e0 + 4 * e8);
            As[4 * e8 + 0][r] = va.x;
            As[4 * e8 + 1][r] = va.y;
            As[4 * e8 + 2][r] = va.z;
            As[4 * e8 + 3][r] = va.w;
            float4 vw = *(const float4*)(W + (size_t)(col0 + r) * EE + e0 + 4 * e8);
            Ws[4 * e8 + 0][r] = vw.x;
            Ws[4 * e8 + 1][r] = vw.y;
            Ws[4 * e8 + 2][r] = vw.z;
            Ws[4 * e8 + 3][r] = vw.w;
        }
        __syncthreads();
#pragma unroll
        for (int e = 0; e < 32; ++e) {
            float4 a4 = *(const float4*)(&As[e][4 * ty]);
            float4 w4 = *(const float4*)(&Ws[e][4 * tx]);
            float av[4] = {a4.x, a4.y, a4.z, a4.w};
            float wv[4] = {w4.x, w4.y, w4.z, w4.w};
#pragma unroll
            for (int i = 0; i < 4; ++i)
#pragma unroll
                for (int j = 0; j < 4; ++j)
                    c[i][j] = fmaf(av[i], wv[j], c[i][j]);
        }
    }

#pragma unroll
    for (int i = 0; i < 4; ++i) {
        float4 o = make_float4(tanh_fast(c[i][0]), tanh_fast(c[i][1]),
                               tanh_fast(c[i][2]), tanh_fast(c[i][3]));
        *(float4*)(C + (size_t)(row0 + 4 * ty + i) * HH + col0 + 4 * tx) = o;
    }
}

// ---------------------------------------------------------------------------
// Scores kernel via tanh addition identity:
//   s[b,q,k] = sum_h w_h * (tq_h + tk_h) / (1 + tq_h * tk_h)
// per elem: num = fma(w, tk, w*tq); den = fma(tq, tk, 1); acc = fma(num, rcp(den), acc)
// Grid: 1024 blocks = b(4) x qtile(64, 8 queries) x ksplit(4, 128 keys).
// Block: 256 threads = 8 warps; warp w owns query qt*8+w.
// Lanes span h (R1-proven structure): lane holds tq/w/w*tq for
// h in {4l..4l+3, 128+4l..128+4l+3} in registers; k tiles staged in smem,
// conflict-free LDS.128. MUFU.RCP (rt=8) is the designed bottleneck.
// ---------------------------------------------------------------------------
__global__ __launch_bounds__(256, 2) void scores_kernel(const float* __restrict__ w_v)
{
    __shared__ __align__(16) float kt[32 * HH];   // 32 KB

    const int tid  = threadIdx.x;
    const int w    = tid >> 5;
    const int lane = tid & 31;

    const int bx = blockIdx.x;
    const int b  = bx >> 8;
    const int qt = (bx >> 2) & 63;
    const int ks = bx & 3;
    const int qi = qt * 8 + w;

    const float* gq = (const float*)g_qv;
    const float* gk = (const float*)g_kv;
    float*       gs = (float*)g_sv;

    const float4* qrow = (const float4*)(gq + (size_t)(b * QQ + qi) * HH);
    const float4  qa = qrow[lane];        // tq for h = 4l..4l+3
    const float4  qb = qrow[32 + lane];   // tq for h = 128+4l..
    const float4* wv4 = (const float4*)w_v;
    const float4  wa = wv4[lane];
    const float4  wb = wv4[32 + lane];
    // w * tq (hoisted numerator part)
    const float4  wqa = make_float4(wa.x * qa.x, wa.y * qa.y, wa.z * qa.z, wa.w * qa.w);
    const float4  wqb = make_float4(wb.x * qb.x, wb.y * qb.y, wb.z * qb.z, wb.w * qb.w);

    for (int t = 0; t < 4; ++t) {
        const int kbase = ks * 128 + t * 32;
        __syncthreads();
        {
            const float4* ksrc = (const float4*)(gk + (size_t)(b * KK + kbase) * HH);
            float4* kdst = (float4*)kt;
#pragma unroll
            for (int j = 0; j < 8; ++j)
                kdst[tid + j * 256] = ksrc[tid + j * 256];
        }
        __syncthreads();

        float* srow = gs + (size_t)(b * QQ + qi) * KK + kbase;

#pragma unroll 2
        for (int kk = 0; kk < 32; ++kk) {
            const float4* krow = (const float4*)(kt + kk * HH);
            const float4 ka = krow[lane];
            const float4 kb = krow[32 + lane];

            // numerators and denominators (all independent -> 8 RCPs in flight)
            float n0 = fmaf(wa.x, ka.x, wqa.x), d0 = fmaf(qa.x, ka.x, 1.0f);
            float n1 = fmaf(wa.y, ka.y, wqa.y), d1 = fmaf(qa.y, ka.y, 1.0f);
            float n2 = fmaf(wa.z, ka.z, wqa.z), d2 = fmaf(qa.z, ka.z, 1.0f);
            float n3 = fmaf(wa.w, ka.w, wqa.w), d3 = fmaf(qa.w, ka.w, 1.0f);
            float n4 = fmaf(wb.x, kb.x, wqb.x), d4 = fmaf(qb.x, kb.x, 1.0f);
            float n5 = fmaf(wb.y, kb.y, wqb.y), d5 = fmaf(qb.y, kb.y, 1.0f);
            float n6 = fmaf(wb.z, kb.z, wqb.z), d6 = fmaf(qb.z, kb.z, 1.0f);
            float n7 = fmaf(wb.w, kb.w, wqb.w), d7 = fmaf(qb.w, kb.w, 1.0f);

            float a0 = n0 * rcp_fast(d0);
            float a1 = n1 * rcp_fast(d1);
            a0 = fmaf(n2, rcp_fast(d2), a0);
            a1 = fmaf(n3, rcp_fast(d3), a1);
            a0 = fmaf(n4, rcp_fast(d4), a0);
            a1 = fmaf(n5, rcp_fast(d5), a1);
            a0 = fmaf(n6, rcp_fast(d6), a0);
            a1 = fmaf(n7, rcp_fast(d7), a1);
            float acc = a0 + a1;

#pragma unroll
            for (int o = 16; o > 0; o >>= 1)
                acc += __shfl_xor_sync(0xffffffffu, acc, o);

            if (lane == 0) srow[kk] = acc;
        }
    }
}

// ---------------------------------------------------------------------------
// Softmax over K + attn @ V (unchanged from R3).
// Grid: 128 blocks = b(4) x qtile(32, 16 queries). Block: 512 threads.
// ---------------------------------------------------------------------------
__global__ __launch_bounds__(512) void softmax_av_kernel(
    const float* __restrict__ values, float* __restrict__ out)
{
    __shared__ __align__(16) float p[16 * 512];
    __shared__ float invs[16];

    const int bx = blockIdx.x;
    const int b  = bx >> 5;
    const int qt = bx & 31;
    const int tid = threadIdx.x;

    {
        const float4* src = (const float4*)((const float*)g_sv + (size_t)(b * QQ + qt * 16) * KK);
        float4* dst = (float4*)p;
#pragma unroll
        for (int j = 0; j < 4; ++j)
            dst[tid + j * 512] = src[tid + j * 512];
    }
    __syncthreads();

    {
        const int w = tid >> 5, lane = tid & 31;
        float* row = p + w * 512;
        float m = -1e30f;
#pragma unroll
        for (int j = 0; j < 16; ++j) m = fmaxf(m, row[lane + 32 * j]);
#pragma unroll
        for (int o = 16; o > 0; o >>= 1)
            m = fmaxf(m, __shfl_xor_sync(0xffffffffu, m, o));
        float sum = 0.0f;
#pragma unroll
        for (int j = 0; j < 16; ++j) {
            float e = __expf(row[lane + 32 * j] - m);
            row[lane + 32 * j] = e;
            sum += e;
        }
#pragma unroll
        for (int o = 16; o > 0; o >>= 1)
            sum += __shfl_xor_sync(0xffffffffu, sum, o);
        if (lane == 0) invs[w] = 1.0f / sum;
    }
    __syncthreads();

    const int dq = tid & 63;
    const int qp = tid >> 6;
    const float* p0r = p + (2 * qp) * 512;
    const float* p1r = p + (2 * qp + 1) * 512;
    const float4* V = (const float4*)(values + (size_t)b * KK * DVV);

    float4 acc0 = make_float4(0.f, 0.f, 0.f, 0.f);
    float4 acc1 = make_float4(0.f, 0.f, 0.f, 0.f);

#pragma unroll 4
    for (int k = 0; k < KK; ++k) {
        const float4 v = V[k * (DVV / 4) + dq];
        const float a = p0r[k];
        const float c = p1r[k];
        acc0.x = fmaf(a, v.x, acc0.x);
        acc0.y = fmaf(a, v.y, acc0.y);
        acc0.z = fmaf(a, v.z, acc0.z);
        acc0.w = fmaf(a, v.w, acc0.w);
        acc1.x = fmaf(c, v.x, acc1.x);
        acc1.y = fmaf(c, v.y, acc1.y);
        acc1.z = fmaf(c, v.z, acc1.z);
        acc1.w = fmaf(c, v.w, acc1.w);
    }

    const float i0 = invs[2 * qp];
    const float i1 = invs[2 * qp + 1];
    acc0.x *= i0; acc0.y *= i0; acc0.z *= i0; acc0.w *= i0;
    acc1.x *= i1; acc1.y *= i1; acc1.z *= i1; acc1.w *= i1;

    const int q0 = qt * 16 + 2 * qp;
    *(float4*)(out + (size_t)(b * QQ + q0) * DVV + 4 * dq)       = acc0;
    *(float4*)(out + (size_t)(b * QQ + q0 + 1) * DVV + 4 * dq)   = acc1;
}

// ---------------------------------------------------------------------------
extern "C" void kernel_launch(void* const* d_in, const int* in_sizes, int n_in,
                              void* d_out, int out_size)
{
    const float* queries = (const float*)d_in[0];
    const float* keys    = (const float*)d_in[1];
    const float* values  = (const float*)d_in[2];
    const float* W_q     = (const float*)d_in[3];
    const float* W_k     = (const float*)d_in[4];
    const float* w_v     = (const float*)d_in[5];
    float* out = (float*)d_out;

    proj_kernel<<<dim3(32, 4, 2), 256>>>(queries, W_q, keys, W_k);
    scores_kernel<<<1024, 256>>>(w_v);
    softmax_av_kernel<<<128, 512>>>(values, out);
}

// round 6
// speedup vs baseline: 1.1605x; 1.1605x over previous
#include <cuda_runtime.h>
#include <cuda_fp16.h>

// AdditiveAttention: B=4, Q=512, K=512, H=256, E=256, DV=256
//   q = queries @ W_q^T            [B,Q,H]
//   k = keys    @ W_k^T            [B,K,H]
//   s[b,q,k] = sum_h w_v[h] * tanh(q[b,q,h] + k[b,k,h])
//   attn = softmax_k(s);  out = attn @ values   [B,Q,Dv]
//
// Scores: dual-pipe tanh. 9/16 of h-elements via MUFU tanh.approx.f16x2,
// 7/16 via FMA-pipe Pade(5,4) rational (cubic-seed + 2 Newton reciprocal).
// Model: MUFU ~16cyc/uop, f16x2 tanh = 2 uops -> both pipes ~288 cyc per
// 4-key group => ~1.7x over all-MUFU.

#define BB 4
#define QQ 512
#define KK 512
#define HH 256
#define EE 256
#define DVV 256

// scratch (device globals: no allocations allowed)
__device__ float4 g_qv[BB * QQ * HH / 4];   // q_proj, 2 MB
__device__ float4 g_kv[BB * KK * HH / 4];   // k_proj, 2 MB
__device__ float4 g_sv[BB * QQ * KK / 4];   // scores, 4 MB

__device__ __forceinline__ __half2 tanh2(__half2 x) {
    unsigned xi = *(unsigned*)&x, yi;
    asm("tanh.approx.f16x2 %0, %1;" : "=r"(yi) : "r"(xi));
    return *(__half2*)&yi;
}

// ---------------------------------------------------------------------------
// Projection GEMM: C[r][h] = sum_e A[r][e] * W[h][e]
// 64x32 tile, 128 threads, 4x4 register tile, e-chunk 32 -> 512 blocks
// (3.5/SM vs 1.7 before; same 16-FMA-per-2-LDS inner ratio as the best proj).
// ---------------------------------------------------------------------------
__global__ __launch_bounds__(128) void proj_kernel(
    const float* __restrict__ Aq, const float* __restrict__ Wq,
    const float* __restrict__ Ak, const float* __restrict__ Wk)
{
    const float* A; const float* W; float* C;
    if (blockIdx.z == 0) { A = Aq; W = Wq; C = (float*)g_qv; }
    else                 { A = Ak; W = Wk; C = (float*)g_kv; }

    const int row0 = blockIdx.x * 64;   // 32 tiles
    const int col0 = blockIdx.y * 32;   // 8 tiles

    __shared__ __align__(16) float As[32][68];   // [e][row]
    __shared__ __align__(16) float Ws[32][36];   // [e][col]

    const int tid = threadIdx.x;
    const int tx = tid & 7;     // 8 col-groups of 4
    const int ty = tid >> 3;    // 16 row-groups of 4

    float c[4][4];
#pragma unroll
    for (int i = 0; i < 4; ++i)
#pragma unroll
        for (int j = 0; j < 4; ++j) c[i][j] = 0.0f;

    for (int e0 = 0; e0 < EE; e0 += 32) {
        __syncthreads();
        // A tile: 64 rows x 32 e = 512 float4 -> 4 per thread
#pragma unroll
        for (int i = 0; i < 4; ++i) {
            const int idx = tid + i * 128;
            const int r  = idx >> 3;
            const int e8 = idx & 7;
            float4 va = *(const float4*)(A + (size_t)(row0 + r) * EE + e0 + 4 * e8);
            As[4 * e8 + 0][r] = va.x;
            As[4 * e8 + 1][r] = va.y;
            As[4 * e8 + 2][r] = va.z;
            As[4 * e8 + 3][r] = va.w;
        }
        // W tile: 32 cols x 32 e = 256 float4 -> 2 per thread
#pragma unroll
        for (int i = 0; i < 2; ++i) {
            const int idx = tid + i * 128;
            const int wr = idx >> 3;
            const int we = idx & 7;
            float4 vw = *(const float4*)(W + (size_t)(col0 + wr) * EE + e0 + 4 * we);
            Ws[4 * we + 0][wr] = vw.x;
            Ws[4 * we + 1][wr] = vw.y;
            Ws[4 * we + 2][wr] = vw.z;
            Ws[4 * we + 3][wr] = vw.w;
        }
        __syncthreads();
#pragma unroll
        for (int e = 0; e < 32; ++e) {
            float4 a4 = *(const float4*)(&As[e][4 * ty]);
            float4 w4 = *(const float4*)(&Ws[e][4 * tx]);
            float av[4] = {a4.x, a4.y, a4.z, a4.w};
            float wv[4] = {w4.x, w4.y, w4.z, w4.w};
#pragma unroll
            for (int i = 0; i < 4; ++i)
#pragma unroll
                for (int j = 0; j < 4; ++j)
                    c[i][j] = fmaf(av[i], wv[j], c[i][j]);
        }
    }

#pragma unroll
    for (int i = 0; i < 4; ++i) {
        float4 o = make_float4(c[i][0], c[i][1], c[i][2], c[i][3]);
        *(float4*)(C + (size_t)(row0 + 4 * ty + i) * EE + col0 + 4 * tx) = o;
    }
}

// ---------------------------------------------------------------------------
// Scores kernel, dual-pipe tanh. R3 structure:
// Grid: 1024 blocks = b(4) x qtile(64, 8 queries) x ksplit(4, 128 keys).
// Block: 256 threads = 8 warps; warp w owns query qt*8+w.
// Lane = kl*8+hg: key kl of 4 concurrent keys; 32 h values as 16 half2.
// Units (m=0..3, c=0..3): m0*,m1*,m2c0 -> MUFU tanh2 (9 units);
//                         m2c1..3,m3* -> FMA-pipe Pade (7 units).
// All Pade constants hoisted before the mainloop.
// ---------------------------------------------------------------------------
__global__ __launch_bounds__(256, 2) void scores_kernel(const float* __restrict__ w_v)
{
    __shared__ __align__(16) __half2 kt[32 * 128];   // 16 KB

    const int tid  = threadIdx.x;
    const int w    = tid >> 5;
    const int lane = tid & 31;
    const int kl   = lane >> 3;
    const int hg   = lane & 7;

    const int bx = blockIdx.x;
    const int b  = bx >> 8;
    const int qt = (bx >> 2) & 63;
    const int ks = bx & 3;
    const int qi = qt * 8 + w;

    const float* gq = (const float*)g_qv;
    const float* gk = (const float*)g_kv;
    float*       gs = (float*)g_sv;

    // hoisted Pade constants (materialized once)
    const __half2 ONE  = __float2half2_rn(1.0f);
    const __half2 TWO  = __float2half2_rn(2.0f);
    const __half2 CL   = __float2half2_rn(3.5f);
    const __half2 NCL  = __float2half2_rn(-3.5f);
    const __half2 A2   = __float2half2_rn(1.058201e-3f);   // 1/945
    const __half2 A1   = __float2half2_rn(0.1111111f);     // 1/9
    const __half2 ND2  = __float2half2_rn(-1.587302e-2f);  // -1/63
    const __half2 ND1  = __float2half2_rn(-0.4444444f);    // -4/9
    const __half2 NONE = __float2half2_rn(-1.0f);
    const __half2 S3   = __float2half2_rn(-1.24864e-3f);
    const __half2 S2   = __float2half2_rn(3.14818e-2f);
    const __half2 S1   = __float2half2_rn(-0.2682161f);
    const __half2 S0   = __float2half2_rn(0.9588652f);

    // FMA-pipe tanh: Pade(5,4), cubic-seed reciprocal + 2 Newton.
    auto tanh_fma = [&](__half2 x) -> __half2 {
        __half2 xc = __hmin2(__hmax2(x, NCL), CL);
        __half2 u  = __hmul2(xc, xc);
        __half2 np = __hfma2(A2, u, A1);
        np = __hfma2(np, u, ONE);
        __half2 N  = __hmul2(xc, np);
        __half2 nD = __hfma2(ND2, u, ND1);
        nD = __hfma2(nD, u, NONE);
        __half2 y  = __hfma2(S3, u, S2);
        y = __hfma2(y, u, S1);
        y = __hfma2(y, u, S0);
        __half2 e  = __hfma2(nD, y, TWO);
        y = __hmul2(y, e);
        e = __hfma2(nD, y, TWO);
        y = __hmul2(y, e);
        return __hmul2(N, y);
    };

    const float4* qrow = (const float4*)(gq + (size_t)(b * QQ + qi) * HH);
    const float4* wv4  = (const float4*)w_v;
    __half2 qp[4][4], wp[4][4];
#pragma unroll
    for (int m = 0; m < 4; ++m) {
        float4 qa = qrow[2 * hg + 16 * m];
        float4 qb = qrow[2 * hg + 16 * m + 1];
        qp[m][0] = __floats2half2_rn(qa.x, qa.y);
        qp[m][1] = __floats2half2_rn(qa.z, qa.w);
        qp[m][2] = __floats2half2_rn(qb.x, qb.y);
        qp[m][3] = __floats2half2_rn(qb.z, qb.w);
        float4 wa = wv4[2 * hg + 16 * m];
        float4 wb = wv4[2 * hg + 16 * m + 1];
        wp[m][0] = __floats2half2_rn(wa.x, wa.y);
        wp[m][1] = __floats2half2_rn(wa.z, wa.w);
        wp[m][2] = __floats2half2_rn(wb.x, wb.y);
        wp[m][3] = __floats2half2_rn(wb.z, wb.w);
    }

    for (int t = 0; t < 4; ++t) {
        const int kbase = ks * 128 + t * 32;
        __syncthreads();
        {
            const float4* ksrc = (const float4*)(gk + (size_t)(b * KK + kbase) * HH);
#pragma unroll
            for (int j = 0; j < 8; ++j) {
                const int idx = tid + j * 256;
                const int key = idx >> 6;
                const int i4  = idx & 63;
                float4 v = ksrc[idx];
                __half2* dst = kt + key * 128 + 2 * i4;
                dst[0] = __floats2half2_rn(v.x, v.y);
                dst[1] = __floats2half2_rn(v.z, v.w);
            }
        }
        __syncthreads();

        float* srow = gs + (size_t)(b * QQ + qi) * KK + kbase;

#pragma unroll 2
        for (int g = 0; g < 8; ++g) {
            const int key = g * 4 + kl;
            const uint4* krow = (const uint4*)(kt + key * 128);

            uint4 kv0 = krow[hg];
            uint4 kv1 = krow[hg + 8];
            uint4 kv2 = krow[hg + 16];
            uint4 kv3 = krow[hg + 24];

            __half2 acc0 = __float2half2_rn(0.f);
            __half2 acc1 = acc0, acc2 = acc0, acc3 = acc0;

            // ---- MUFU units (9): m0c0..3, m1c0..3, m2c0 ----
            acc0 = __hfma2(wp[0][0], tanh2(__hadd2(qp[0][0], *(__half2*)&kv0.x)), acc0);
            acc1 = __hfma2(wp[0][1], tanh2(__hadd2(qp[0][1], *(__half2*)&kv0.y)), acc1);
            acc2 = __hfma2(wp[0][2], tanh2(__hadd2(qp[0][2], *(__half2*)&kv0.z)), acc2);
            acc3 = __hfma2(wp[0][3], tanh2(__hadd2(qp[0][3], *(__half2*)&kv0.w)), acc3);
            acc0 = __hfma2(wp[1][0], tanh2(__hadd2(qp[1][0], *(__half2*)&kv1.x)), acc0);
            acc1 = __hfma2(wp[1][1], tanh2(__hadd2(qp[1][1], *(__half2*)&kv1.y)), acc1);
            acc2 = __hfma2(wp[1][2], tanh2(__hadd2(qp[1][2], *(__half2*)&kv1.z)), acc2);
            acc3 = __hfma2(wp[1][3], tanh2(__hadd2(qp[1][3], *(__half2*)&kv1.w)), acc3);
            acc0 = __hfma2(wp[2][0], tanh2(__hadd2(qp[2][0], *(__half2*)&kv2.x)), acc0);
            // ---- FMA-pipe units (7): m2c1..3, m3c0..3 ----
            acc1 = __hfma2(wp[2][1], tanh_fma(__hadd2(qp[2][1], *(__half2*)&kv2.y)), acc1);
            acc2 = __hfma2(wp[2][2], tanh_fma(__hadd2(qp[2][2], *(__half2*)&kv2.z)), acc2);
            acc3 = __hfma2(wp[2][3], tanh_fma(__hadd2(qp[2][3], *(__half2*)&kv2.w)), acc3);
            acc0 = __hfma2(wp[3][0], tanh_fma(__hadd2(qp[3][0], *(__half2*)&kv3.x)), acc0);
            acc1 = __hfma2(wp[3][1], tanh_fma(__hadd2(qp[3][1], *(__half2*)&kv3.y)), acc1);
            acc2 = __hfma2(wp[3][2], tanh_fma(__hadd2(qp[3][2], *(__half2*)&kv3.z)), acc2);
            acc3 = __hfma2(wp[3][3], tanh_fma(__hadd2(qp[3][3], *(__half2*)&kv3.w)), acc3);

            float2 f0 = __half22float2(acc0);
            float2 f1 = __half22float2(acc1);
            float2 f2 = __half22float2(acc2);
            float2 f3 = __half22float2(acc3);
            float s = ((f0.x + f0.y) + (f1.x + f1.y)) +
                      ((f2.x + f2.y) + (f3.x + f3.y));

            s += __shfl_xor_sync(0xffffffffu, s, 1);
            s += __shfl_xor_sync(0xffffffffu, s, 2);
            s += __shfl_xor_sync(0xffffffffu, s, 4);
            float v = __shfl_sync(0xffffffffu, s, (lane & 3) * 8);
            if (lane < 4) srow[g * 4 + lane] = v;
        }
    }
}

// ---------------------------------------------------------------------------
// Softmax over K + attn @ V (unchanged).
// Grid: 128 blocks = b(4) x qtile(32, 16 queries). Block: 512 threads.
// ---------------------------------------------------------------------------
__global__ __launch_bounds__(512) void softmax_av_kernel(
    const float* __restrict__ values, float* __restrict__ out)
{
    __shared__ __align__(16) float p[16 * 512];
    __shared__ float invs[16];

    const int bx = blockIdx.x;
    const int b  = bx >> 5;
    const int qt = bx & 31;
    const int tid = threadIdx.x;

    {
        const float4* src = (const float4*)((const float*)g_sv + (size_t)(b * QQ + qt * 16) * KK);
        float4* dst = (float4*)p;
#pragma unroll
        for (int j = 0; j < 4; ++j)
            dst[tid + j * 512] = src[tid + j * 512];
    }
    __syncthreads();

    {
        const int w = tid >> 5, lane = tid & 31;
        float* row = p + w * 512;
        float m = -1e30f;
#pragma unroll
        for (int j = 0; j < 16; ++j) m = fmaxf(m, row[lane + 32 * j]);
#pragma unroll
        for (int o = 16; o > 0; o >>= 1)
            m = fmaxf(m, __shfl_xor_sync(0xffffffffu, m, o));
        float sum = 0.0f;
#pragma unroll
        for (int j = 0; j < 16; ++j) {
            float e = __expf(row[lane + 32 * j] - m);
            row[lane + 32 * j] = e;
            sum += e;
        }
#pragma unroll
        for (int o = 16; o > 0; o >>= 1)
            sum += __shfl_xor_sync(0xffffffffu, sum, o);
        if (lane == 0) invs[w] = 1.0f / sum;
    }
    __syncthreads();

    const int dq = tid & 63;
    const int qp = tid >> 6;
    const float* p0r = p + (2 * qp) * 512;
    const float* p1r = p + (2 * qp + 1) * 512;
    const float4* V = (const float4*)(values + (size_t)b * KK * DVV);

    float4 acc0 = make_float4(0.f, 0.f, 0.f, 0.f);
    float4 acc1 = make_float4(0.f, 0.f, 0.f, 0.f);

#pragma unroll 4
    for (int k = 0; k < KK; ++k) {
        const float4 v = V[k * (DVV / 4) + dq];
        const float a = p0r[k];
        const float c = p1r[k];
        acc0.x = fmaf(a, v.x, acc0.x);
        acc0.y = fmaf(a, v.y, acc0.y);
        acc0.z = fmaf(a, v.z, acc0.z);
        acc0.w = fmaf(a, v.w, acc0.w);
        acc1.x = fmaf(c, v.x, acc1.x);
        acc1.y = fmaf(c, v.y, acc1.y);
        acc1.z = fmaf(c, v.z, acc1.z);
        acc1.w = fmaf(c, v.w, acc1.w);
    }

    const float i0 = invs[2 * qp];
    const float i1 = invs[2 * qp + 1];
    acc0.x *= i0; acc0.y *= i0; acc0.z *= i0; acc0.w *= i0;
    acc1.x *= i1; acc1.y *= i1; acc1.z *= i1; acc1.w *= i1;

    const int q0 = qt * 16 + 2 * qp;
    *(float4*)(out + (size_t)(b * QQ + q0) * DVV + 4 * dq)       = acc0;
    *(float4*)(out + (size_t)(b * QQ + q0 + 1) * DVV + 4 * dq)   = acc1;
}

// ---------------------------------------------------------------------------
extern "C" void kernel_launch(void* const* d_in, const int* in_sizes, int n_in,
                              void* d_out, int out_size)
{
    const float* queries = (const float*)d_in[0];
    const float* keys    = (const float*)d_in[1];
    const float* values  = (const float*)d_in[2];
    const float* W_q     = (const float*)d_in[3];
    const float* W_k     = (const float*)d_in[4];
    const float* w_v     = (const float*)d_in[5];
    float* out = (float*)d_out;

    proj_kernel<<<dim3(32, 8, 2), 128>>>(queries, W_q, keys, W_k);
    scores_kernel<<<1024, 256>>>(w_v);
    softmax_av_kernel<<<128, 512>>>(values, out);
}